// round 16
// baseline (speedup 1.0000x reference)
#include <cuda_runtime.h>
#include <cstdint>

// Problem dims
#define BSZ   4096
#define LSEQ  64
#define EDIM  32
#define HDIM  32
#define GDIM  256
#define F2DIM 512
#define ADIM  1000
#define NSF   32768   // 8 * BSZ
#define NS    36864   // 9 * BSZ
#define VSIZE 50000
#define VPAD  50048   // 391 * 128

typedef unsigned long long ull;

// ---------------- scratch (device globals: allocation-free) ----------------
__device__ float d_hq[BSZ * HDIM];                       // [4096, 32]
__device__ float d_X0[(size_t)NSF * 64];                 // [32768, 64]
__device__ float d_X1[(size_t)NSF * GDIM];               // [32768, 256]
__device__ float d_X2[(size_t)NSF * GDIM];               // [32768, 256]
__device__ float d_gsum[(size_t)BSZ * GDIM];             // [4096, 256]
__device__ float d_Y1[(size_t)BSZ * GDIM];               // [4096, 256]
__device__ float d_Y2[(size_t)BSZ * F2DIM];              // [4096, 512]
__device__ float d_brel[8 * GDIM];                       // per-relation g1 bias

// Pre-split Whh for tensor-core LSTM: [n=g*32+j][k], padded to 36, (hi,lo) tf32
__device__ uint2 d_whhpkq[128 * 36];
__device__ uint2 d_whhpks[128 * 36];

// Pre-split GEMM weights (tf32 hi,lo), packed dense K per layer:
#define OFF_G1 0
#define OFF_G2 16384
#define OFF_G3 81920
#define OFF_G4 147456
#define OFF_F1 212992
#define OFF_F2 278528
#define OFF_F3 409600
#define WSP_TOTAL 921600
__device__ uint2 d_wsp[WSP_TOTAL];

// Precomputed input projections: xproj[v][n = g*32+j] = Wih·emb[v] + b  (native layout)
__device__ float d_xpq[(size_t)VPAD * 128];
__device__ float d_xps[(size_t)VPAD * 128];

struct SfPtrs { const int* p[8]; };

__device__ __forceinline__ float ftanh_(float x) {
    float r;
    asm("tanh.approx.f32 %0, %1;" : "=f"(r) : "f"(x));
    return r;
}
__device__ __forceinline__ float fsig(float x) {
    return fmaf(ftanh_(0.5f * x), 0.5f, 0.5f);
}
__device__ __forceinline__ uint32_t f2tf32(float x) {
    uint32_t r; asm("cvt.rna.tf32.f32 %0, %1;" : "=r"(r) : "f"(x)); return r;
}
__device__ __forceinline__ void tf32_split(float x, uint32_t& hi, uint32_t& lo) {
    hi = f2tf32(x);
    lo = f2tf32(x - __uint_as_float(hi));
}
__device__ __forceinline__ void mma_tf32(float* d, const uint32_t* a, const uint32_t* b) {
    asm volatile(
        "mma.sync.aligned.m16n8k8.row.col.f32.tf32.tf32.f32 "
        "{%0,%1,%2,%3}, {%4,%5,%6,%7}, {%8,%9}, {%0,%1,%2,%3};"
        : "+f"(d[0]), "+f"(d[1]), "+f"(d[2]), "+f"(d[3])
        : "r"(a[0]), "r"(a[1]), "r"(a[2]), "r"(a[3]), "r"(b[0]), "r"(b[1]));
}

// ---------------------------------------------------------------------------
// Pack Whh into pre-split tf32 (hi,lo) with row pad 36.
// ---------------------------------------------------------------------------
__global__ void pack_kernel(const float* __restrict__ qWhh, const float* __restrict__ sWhh)
{
    int idx = blockIdx.x * blockDim.x + threadIdx.x;   // 0 .. 128*36-1
    if (idx < 128 * 36) {
        int n = idx / 36, k = idx % 36;
        float vq = (k < 32) ? qWhh[n * 32 + k] : 0.f;
        float vs = (k < 32) ? sWhh[n * 32 + k] : 0.f;
        uint32_t hi, lo;
        tf32_split(vq, hi, lo);
        d_whhpkq[idx] = make_uint2(hi, lo);
        tf32_split(vs, hi, lo);
        d_whhpks[idx] = make_uint2(hi, lo);
    }
}

// ONE fused pre-split kernel for all 7 GEMM weight matrices.
__global__ void pack_w_all_kernel(
    const float* __restrict__ g1W, const float* __restrict__ g2W,
    const float* __restrict__ g3W, const float* __restrict__ g4W,
    const float* __restrict__ f1W, const float* __restrict__ f2W,
    const float* __restrict__ f3W)
{
    int idx = blockIdx.x * blockDim.x + threadIdx.x;
    if (idx >= WSP_TOTAL) return;
    const float* src;
    int K, ldw, base;
    if      (idx < OFF_G2) { src = g1W; K = 64;    ldw = 65;    base = OFF_G1; }
    else if (idx < OFF_G3) { src = g2W; K = GDIM;  ldw = GDIM;  base = OFF_G2; }
    else if (idx < OFF_G4) { src = g3W; K = GDIM;  ldw = GDIM;  base = OFF_G3; }
    else if (idx < OFF_F1) { src = g4W; K = GDIM;  ldw = GDIM;  base = OFF_G4; }
    else if (idx < OFF_F2) { src = f1W; K = GDIM;  ldw = GDIM;  base = OFF_F1; }
    else if (idx < OFF_F3) { src = f2W; K = GDIM;  ldw = GDIM;  base = OFF_F2; }
    else                   { src = f3W; K = F2DIM; ldw = F2DIM; base = OFF_F3; }
    int rel = idx - base;
    int n = rel / K, k = rel % K;
    uint32_t hi, lo;
    tf32_split(src[(size_t)n * ldw + k], hi, lo);
    d_wsp[idx] = make_uint2(hi, lo);
}

// Per-relation g1 bias: brel[r][n] = g1b[n] + r * g1W[n][64]
__global__ void bias_rel_kernel(const float* __restrict__ g1W, const float* __restrict__ g1b)
{
    int idx = blockIdx.x * blockDim.x + threadIdx.x;
    if (idx < 8 * GDIM) {
        int r = idx >> 8, n = idx & 255;
        d_brel[idx] = g1b[n] + (float)r * g1W[n * 65 + 64];
    }
}

// ---------------------------------------------------------------------------
// Tensor-core LSTM recurrence (R12 exact). Block = 64 samples, 128 threads,
// warp owns 16 sample rows. NO __syncthreads in loop.
// ---------------------------------------------------------------------------
#define LSTM_SMEM_BYTES ((128 * 36 + 64 * 36) * 8)   // 55296 B

__global__ void __launch_bounds__(128, 3) lstm_tc_kernel(const int* __restrict__ q, SfPtrs sf)
{
    extern __shared__ uint2 sm2[];
    uint2* sWhh = sm2;              // [128][36]
    uint2* sH   = sm2 + 128 * 36;   // [64][36]

    const int tid  = threadIdx.x;
    const int lane = tid & 31;
    const int wm   = (tid >> 5) * 16;
    const int lr   = lane >> 2;
    const int lc   = lane & 3;

    const bool isQ = (blockIdx.x < (BSZ / 64));
    const uint2* wsrc = isQ ? d_whhpkq : d_whhpks;
    const float* xp   = isQ ? d_xpq    : d_xps;

    for (int i = tid; i < 128 * 36; i += 128) sWhh[i] = wsrc[i];
    for (int i = tid; i < 64 * 36; i += 128) sH[i] = make_uint2(0u, 0u);
    __syncthreads();

    const int s0 = blockIdx.x * 64 + wm + lr;
    const int s1 = s0 + 8;
    const int *pt0, *pt1;
    if (isQ) {
        pt0 = q + (size_t)s0 * LSEQ;
        pt1 = q + (size_t)s1 * LSEQ;
    } else {
        int ss0 = s0 - BSZ;
        int r = ss0 >> 12;
        pt0 = sf.p[r] + (size_t)(ss0 & (BSZ - 1)) * LSEQ;
        pt1 = sf.p[r] + (size_t)((s1 - BSZ) & (BSZ - 1)) * LSEQ;
    }

    float c[16];
#pragma unroll
    for (int i = 0; i < 16; i++) c[i] = 0.f;

    for (int t = 0; t < LSEQ; t++) {
        const int tok0 = __ldg(&pt0[t]);
        const int tok1 = __ldg(&pt1[t]);
        const float2* xr0 = reinterpret_cast<const float2*>(xp + (size_t)tok0 * 128);
        const float2* xr1 = reinterpret_cast<const float2*>(xp + (size_t)tok1 * 128);

        float acc[16][4];
#pragma unroll
        for (int nt = 0; nt < 16; nt++) {
            float2 g0 = __ldg(&xr0[nt * 4 + lc]);
            float2 g1 = __ldg(&xr1[nt * 4 + lc]);
            acc[nt][0] = g0.x; acc[nt][1] = g0.y;
            acc[nt][2] = g1.x; acc[nt][3] = g1.y;
        }

#pragma unroll
        for (int kc = 0; kc < 4; kc++) {
            const int kb = kc * 8;
            const uint2 a0 = sH[(wm + lr) * 36 + kb + lc];
            const uint2 a1 = sH[(wm + lr + 8) * 36 + kb + lc];
            const uint2 a2 = sH[(wm + lr) * 36 + kb + lc + 4];
            const uint2 a3 = sH[(wm + lr + 8) * 36 + kb + lc + 4];
            const uint32_t ah[4] = { a0.x, a1.x, a2.x, a3.x };
            const uint32_t al[4] = { a0.y, a1.y, a2.y, a3.y };
#pragma unroll
            for (int nt = 0; nt < 16; nt++) {
                const uint2 b0 = sWhh[(nt * 8 + lr) * 36 + kb + lc];
                const uint2 b1 = sWhh[(nt * 8 + lr) * 36 + kb + lc + 4];
                const uint32_t bh[2] = { b0.x, b1.x };
                const uint32_t bl[2] = { b0.y, b1.y };
                mma_tf32(acc[nt], ah, bh);
                mma_tf32(acc[nt], ah, bl);
                mma_tf32(acc[nt], al, bh);
            }
        }

#pragma unroll
        for (int qx = 0; qx < 4; qx++) {
#pragma unroll
            for (int cix = 0; cix < 4; cix++) {
                const float gi = acc[0 * 4 + qx][cix];
                const float gf = acc[1 * 4 + qx][cix];
                const float gg = acc[2 * 4 + qx][cix];
                const float go = acc[3 * 4 + qx][cix];
                const int idx = qx * 4 + cix;
                float cc = c[idx];
                cc = fsig(gf) * cc + fsig(gi) * ftanh_(gg);
                c[idx] = cc;
                const float hv = fsig(go) * ftanh_(cc);
                uint32_t hi, lo;
                tf32_split(hv, hi, lo);
                const int row = wm + lr + (cix >> 1) * 8;
                const int k   = qx * 8 + 2 * lc + (cix & 1);
                sH[row * 36 + k] = make_uint2(hi, lo);
            }
        }
        __syncwarp();
    }

    {
        const int rl = wm + (lane >> 1);
        const int kb = (lane & 1) * 16;
        float hv[16];
#pragma unroll
        for (int i = 0; i < 16; i++) {
            uint2 v = sH[rl * 36 + kb + i];
            hv[i] = __uint_as_float(v.x) + __uint_as_float(v.y);
        }
        const int sg = blockIdx.x * 64 + rl;
        float* dst = isQ ? (d_hq + (size_t)sg * HDIM + kb)
                         : (d_X0 + (size_t)(sg - BSZ) * 64 + kb);
        float4* d4 = reinterpret_cast<float4*>(dst);
#pragma unroll
        for (int i = 0; i < 4; i++)
            d4[i] = make_float4(hv[4 * i], hv[4 * i + 1], hv[4 * i + 2], hv[4 * i + 3]);
    }
}

// X0[s, 32:64] = hq[b]
__global__ void build_x0_kernel()
{
    int s = blockIdx.x * blockDim.x + threadIdx.x;
    if (s >= NSF) return;
    int b = s & (BSZ - 1);
    const float4* src = reinterpret_cast<const float4*>(d_hq + (size_t)b * HDIM);
    float4* dst = reinterpret_cast<float4*>(d_X0 + (size_t)s * 64 + 32);
#pragma unroll
    for (int i = 0; i < 8; i++) dst[i] = src[i];
}

// ---------------------------------------------------------------------------
// fp32 GEMM (double-buffered) — used only for the xproj precompute (K=32).
// ---------------------------------------------------------------------------
__global__ __launch_bounds__(256, 2) void gemm_kernel(
    const float* __restrict__ A, const float* __restrict__ W,
    const float* __restrict__ bias, float* __restrict__ C,
    int Mr, int N, int K, int lda, int ldw, int doRelu, int biasPerRel)
{
    __shared__ __align__(16) float sA[2][16][132];
    __shared__ __align__(16) float sW[2][16][68];

    const int bm = blockIdx.y * 128;
    const int bn = blockIdx.x * 64;
    const int tid = threadIdx.x;
    const int tx = tid & 15;
    const int ty = tid >> 4;

    float acc[8][4];
#pragma unroll
    for (int i = 0; i < 8; i++)
#pragma unroll
        for (int j = 0; j < 4; j++) acc[i][j] = 0.f;

    const int nk = (K + 15) >> 4;

#pragma unroll
    for (int i = 0; i < 8; i++) {
        int e = tid + i * 256; int m = e >> 4; int kk = e & 15;
        sA[0][kk][m] = (kk < K && (bm + m) < Mr) ? A[(size_t)(bm + m) * lda + kk] : 0.f;
    }
#pragma unroll
    for (int i = 0; i < 4; i++) {
        int e = tid + i * 256; int n = e >> 4; int kk = e & 15;
        sW[0][kk][n] = (kk < K && (bn + n) < N) ? W[(size_t)(bn + n) * ldw + kk] : 0.f;
    }
    __syncthreads();

    for (int kt = 0; kt < nk; kt++) {
        const int cur = kt & 1;
        float pa[8], pw[4];
        const bool has = (kt + 1 < nk);
        if (has) {
            int k0 = (kt + 1) << 4;
#pragma unroll
            for (int i = 0; i < 8; i++) {
                int e = tid + i * 256; int m = e >> 4; int kk = e & 15; int gk = k0 + kk;
                pa[i] = (gk < K && (bm + m) < Mr) ? A[(size_t)(bm + m) * lda + gk] : 0.f;
            }
#pragma unroll
            for (int i = 0; i < 4; i++) {
                int e = tid + i * 256; int n = e >> 4; int kk = e & 15; int gk = k0 + kk;
                pw[i] = (gk < K && (bn + n) < N) ? W[(size_t)(bn + n) * ldw + gk] : 0.f;
            }
        }
#pragma unroll
        for (int kk = 0; kk < 16; kk++) {
            float a[8], w[4];
            float4 a0 = *reinterpret_cast<const float4*>(&sA[cur][kk][ty * 8]);
            float4 a1 = *reinterpret_cast<const float4*>(&sA[cur][kk][ty * 8 + 4]);
            float4 w0 = *reinterpret_cast<const float4*>(&sW[cur][kk][tx * 4]);
            a[0]=a0.x; a[1]=a0.y; a[2]=a0.z; a[3]=a0.w;
            a[4]=a1.x; a[5]=a1.y; a[6]=a1.z; a[7]=a1.w;
            w[0]=w0.x; w[1]=w0.y; w[2]=w0.z; w[3]=w0.w;
#pragma unroll
            for (int i = 0; i < 8; i++)
#pragma unroll
                for (int j = 0; j < 4; j++) acc[i][j] += a[i] * w[j];
        }
        if (has) {
            const int nxt = cur ^ 1;
#pragma unroll
            for (int i = 0; i < 8; i++) {
                int e = tid + i * 256; int m = e >> 4; int kk = e & 15;
                sA[nxt][kk][m] = pa[i];
            }
#pragma unroll
            for (int i = 0; i < 4; i++) {
                int e = tid + i * 256; int n = e >> 4; int kk = e & 15;
                sW[nxt][kk][n] = pw[i];
            }
            __syncthreads();
        }
    }

    const float* brow = biasPerRel ? (bias + (size_t)(bm >> 12) * N) : bias;
#pragma unroll
    for (int i = 0; i < 8; i++) {
        int m = bm + ty * 8 + i;
#pragma unroll
        for (int j = 0; j < 4; j++) {
            int n = bn + tx * 4 + j;
            if (n < N) {
                float v = acc[i][j] + brow[n];
                if (doRelu) v = fmaxf(v, 0.f);
                C[(size_t)m * N + n] = v;
            }
        }
    }
}

// ---------------------------------------------------------------------------
// 3xTF32 tensor-core GEMM, 128x128 block tile, pre-split weights.
// 8 warps (4m x 2n), warp tile 32m x 64n. Dynamic smem 54KB.
// C[M,N] = act(A[M,K(lda)] @ W[N,K]^T + bias). M%128==0, K%32==0, lda%4==0.
// ---------------------------------------------------------------------------
#define TC_SMEM_BYTES (128 * 36 * 4 + 128 * 36 * 8)   // 55296 B

__global__ __launch_bounds__(256) void gemm_tc_kernel(
    const float* __restrict__ A, const uint2* __restrict__ Wsp,
    const float* __restrict__ bias, float* __restrict__ C,
    int N, int K, int lda, int doRelu, int biasPerRel)
{
    extern __shared__ char smraw[];
    uint2* sW2 = reinterpret_cast<uint2*>(smraw);                 // [128][36]
    float* sA  = reinterpret_cast<float*>(smraw + 128 * 36 * 8);  // [128][36]

    const int bm = blockIdx.y * 128;
    const int bn = blockIdx.x * 128;
    const int tid  = threadIdx.x;
    const int lane = tid & 31;
    const int wid  = tid >> 5;
    const int warpM = wid & 3;
    const int warpN = wid >> 2;
    const int wm = warpM * 32;
    const int wn = warpN * 64;
    const int lr = lane >> 2;
    const int lc = lane & 3;

    float acc[2][8][4];
#pragma unroll
    for (int mt = 0; mt < 2; mt++)
#pragma unroll
        for (int nt = 0; nt < 8; nt++)
#pragma unroll
            for (int r = 0; r < 4; r++) acc[mt][nt][r] = 0.f;

    for (int k0 = 0; k0 < K; k0 += 32) {
        // A tile 128x32 floats (1024 float4 / 256 thr = 4 each)
#pragma unroll
        for (int i = 0; i < 4; i++) {
            int e = tid + i * 256;
            int m = e >> 3;
            int kq = e & 7;
            float4 v = *reinterpret_cast<const float4*>(&A[(size_t)(bm + m) * lda + k0 + kq * 4]);
            *reinterpret_cast<float4*>(&sA[m * 36 + kq * 4]) = v;
        }
        // W tile: 128 rows x 32 k of uint2 = 128 x 16 uint4 = 2048 uint4 (8 per thread)
#pragma unroll
        for (int i = 0; i < 8; i++) {
            int e = tid + i * 256;     // 0..2047
            int n = e >> 4;            // 0..127
            int kq = e & 15;           // uint4 chunk (2 uint2 = 2 k)
            uint4 v = make_uint4(0u, 0u, 0u, 0u);
            if ((bn + n) < N)
                v = *reinterpret_cast<const uint4*>(&Wsp[(size_t)(bn + n) * K + k0 + kq * 2]);
            *reinterpret_cast<uint4*>(&sW2[n * 36 + kq * 2]) = v;
        }
        __syncthreads();

#pragma unroll
        for (int kc = 0; kc < 4; kc++) {
            const int kb = kc * 8;
            uint32_t ahi[2][4], alo[2][4];
#pragma unroll
            for (int mt = 0; mt < 2; mt++) {
                int r0 = wm + mt * 16 + lr;
                float a0 = sA[r0 * 36 + kb + lc];
                float a1 = sA[(r0 + 8) * 36 + kb + lc];
                float a2 = sA[r0 * 36 + kb + lc + 4];
                float a3 = sA[(r0 + 8) * 36 + kb + lc + 4];
                tf32_split(a0, ahi[mt][0], alo[mt][0]);
                tf32_split(a1, ahi[mt][1], alo[mt][1]);
                tf32_split(a2, ahi[mt][2], alo[mt][2]);
                tf32_split(a3, ahi[mt][3], alo[mt][3]);
            }
#pragma unroll
            for (int nt = 0; nt < 8; nt++) {
                const uint2 b0 = sW2[(wn + nt * 8 + lr) * 36 + kb + lc];
                const uint2 b1 = sW2[(wn + nt * 8 + lr) * 36 + kb + lc + 4];
                const uint32_t bh[2] = { b0.x, b1.x };
                const uint32_t bl[2] = { b0.y, b1.y };
#pragma unroll
                for (int mt = 0; mt < 2; mt++) {
                    mma_tf32(acc[mt][nt], ahi[mt], bh);
                    mma_tf32(acc[mt][nt], ahi[mt], bl);
                    mma_tf32(acc[mt][nt], alo[mt], bh);
                }
            }
        }
        __syncthreads();
    }

    const float* brow = biasPerRel ? (bias + (size_t)(bm >> 12) * N) : bias;
#pragma unroll
    for (int mt = 0; mt < 2; mt++) {
#pragma unroll
        for (int nt = 0; nt < 8; nt++) {
            int r = bm + wm + mt * 16 + lr;
            int n = bn + wn + nt * 8 + 2 * lc;
            if (n < N) {
                float bsx = brow[n], bsy = brow[n + 1];
                float2 v0 = make_float2(acc[mt][nt][0] + bsx, acc[mt][nt][1] + bsy);
                float2 v1 = make_float2(acc[mt][nt][2] + bsx, acc[mt][nt][3] + bsy);
                if (doRelu) {
                    v0.x = fmaxf(v0.x, 0.f); v0.y = fmaxf(v0.y, 0.f);
                    v1.x = fmaxf(v1.x, 0.f); v1.y = fmaxf(v1.y, 0.f);
                }
                *reinterpret_cast<float2*>(&C[(size_t)r * N + n]) = v0;
                *reinterpret_cast<float2*>(&C[(size_t)(r + 8) * N + n]) = v1;
            }
        }
    }
}

// gsum[b,n] = sum_{r=0..7} X2[r*BSZ + b, n]
__global__ void reduce8_kernel()
{
    int idx = blockIdx.x * 256 + threadIdx.x;
    int b = idx >> 8;
    int n = idx & 255;
    float sum = 0.f;
#pragma unroll
    for (int r = 0; r < 8; r++)
        sum += d_X2[((size_t)(r * BSZ + b)) * GDIM + n];
    d_gsum[idx] = sum;
}

// ---------------------------------------------------------------------------
extern "C" void kernel_launch(void* const* d_in, const int* in_sizes, int n_in,
                              void* d_out, int out_size)
{
    const int*   q    = (const int*)d_in[0];
    SfPtrs sf;
    for (int i = 0; i < 8; i++) sf.p[i] = (const int*)d_in[1 + i];
    const float* emb  = (const float*)d_in[9];
    const float* qWih = (const float*)d_in[10];
    const float* qWhh = (const float*)d_in[11];
    const float* qb   = (const float*)d_in[12];
    const float* sWih = (const float*)d_in[13];
    const float* sWhh = (const float*)d_in[14];
    const float* sb   = (const float*)d_in[15];
    const float* g1W  = (const float*)d_in[16];
    const float* g1b  = (const float*)d_in[17];
    const float* g2W  = (const float*)d_in[18];
    const float* g2b  = (const float*)d_in[19];
    const float* g3W  = (const float*)d_in[20];
    const float* g3b  = (const float*)d_in[21];
    const float* g4W  = (const float*)d_in[22];
    const float* g4b  = (const float*)d_in[23];
    const float* f1W  = (const float*)d_in[24];
    const float* f1b  = (const float*)d_in[25];
    const float* f2W  = (const float*)d_in[26];
    const float* f2b  = (const float*)d_in[27];
    const float* f3W  = (const float*)d_in[28];
    const float* f3b  = (const float*)d_in[29];
    float* out = (float*)d_out;

    void *pX0, *pX1, *pX2, *pGsum, *pY1, *pY2, *pBrel, *pXpq, *pXps, *pWsp;
    cudaGetSymbolAddress(&pX0,   d_X0);
    cudaGetSymbolAddress(&pX1,   d_X1);
    cudaGetSymbolAddress(&pX2,   d_X2);
    cudaGetSymbolAddress(&pGsum, d_gsum);
    cudaGetSymbolAddress(&pY1,   d_Y1);
    cudaGetSymbolAddress(&pY2,   d_Y2);
    cudaGetSymbolAddress(&pBrel, d_brel);
    cudaGetSymbolAddress(&pXpq,  d_xpq);
    cudaGetSymbolAddress(&pXps,  d_xps);
    cudaGetSymbolAddress(&pWsp,  d_wsp);
    const float* X0 = (const float*)pX0;
    float* X1 = (float*)pX1;
    float* X2 = (float*)pX2;
    float* Gs = (float*)pGsum;
    float* Y1 = (float*)pY1;
    float* Y2 = (float*)pY2;
    const float* Brel = (const float*)pBrel;
    uint2* Wsp = (uint2*)pWsp;

    static bool attr_set = false;
    if (!attr_set) {
        cudaFuncSetAttribute(lstm_tc_kernel, cudaFuncAttributeMaxDynamicSharedMemorySize,
                             LSTM_SMEM_BYTES);
        cudaFuncSetAttribute(gemm_tc_kernel, cudaFuncAttributeMaxDynamicSharedMemorySize,
                             TC_SMEM_BYTES);
        attr_set = true;
    }

    // 0) pack Whh + per-relation g1 bias + ONE fused weight pre-split
    pack_kernel<<<18, 256>>>(qWhh, sWhh);
    bias_rel_kernel<<<8, 256>>>(g1W, g1b);
    pack_w_all_kernel<<<(WSP_TOTAL + 255) / 256, 256>>>(g1W, g2W, g3W, g4W, f1W, f2W, f3W);

    // 0b) precompute input projections: xproj = emb @ Wih^T + b (native layout)
    gemm_kernel<<<dim3(2, VPAD / 128), 256>>>(emb, qWih, qb, (float*)pXpq,
                                              VSIZE, 128, 32, 32, 32, 0, 0);
    gemm_kernel<<<dim3(2, VPAD / 128), 256>>>(emb, sWih, sb, (float*)pXps,
                                              VSIZE, 128, 32, 32, 32, 0, 0);

    // 1) tensor-core LSTM recurrence (q + 8 sf streams)
    lstm_tc_kernel<<<NS / 64, 128, LSTM_SMEM_BYTES>>>(q, sf);

    // 2) assemble g1 input [32768, 64]
    build_x0_kernel<<<(NSF + 255) / 256, 256>>>();

    // 3) g-MLP on tensor cores (3xTF32, 128x128 tiles, pre-split weights)
    gemm_tc_kernel<<<dim3(GDIM / 128, NSF / 128), 256, TC_SMEM_BYTES>>>(X0, Wsp + OFF_G1, Brel, X1, GDIM, 64, 64, 1, 1);
    gemm_tc_kernel<<<dim3(GDIM / 128, NSF / 128), 256, TC_SMEM_BYTES>>>(X1, Wsp + OFF_G2, g2b, X2, GDIM, GDIM, GDIM, 1, 0);
    gemm_tc_kernel<<<dim3(GDIM / 128, NSF / 128), 256, TC_SMEM_BYTES>>>(X2, Wsp + OFF_G3, g3b, X1, GDIM, GDIM, GDIM, 1, 0);
    gemm_tc_kernel<<<dim3(GDIM / 128, NSF / 128), 256, TC_SMEM_BYTES>>>(X1, Wsp + OFF_G4, g4b, X2, GDIM, GDIM, GDIM, 1, 0);

    // 4) segment-sum over 8 relations
    reduce8_kernel<<<(BSZ * GDIM) / 256, 256>>>();

    // 5) f-head on tensor cores
    gemm_tc_kernel<<<dim3(GDIM / 128,  BSZ / 128), 256, TC_SMEM_BYTES>>>(Gs, Wsp + OFF_F1, f1b, Y1, GDIM,  GDIM,  GDIM,  1, 0);
    gemm_tc_kernel<<<dim3(F2DIM / 128, BSZ / 128), 256, TC_SMEM_BYTES>>>(Y1, Wsp + OFF_F2, f2b, Y2, F2DIM, GDIM,  GDIM,  1, 0);
    gemm_tc_kernel<<<dim3((ADIM + 127) / 128, BSZ / 128), 256, TC_SMEM_BYTES>>>(Y2, Wsp + OFF_F3, f3b, out, ADIM, F2DIM, F2DIM, 0, 0);
}

// round 17
// speedup vs baseline: 1.1535x; 1.1535x over previous
#include <cuda_runtime.h>
#include <cstdint>

// Problem dims
#define BSZ   4096
#define LSEQ  64
#define EDIM  32
#define HDIM  32
#define GDIM  256
#define F2DIM 512
#define ADIM  1000
#define NSF   32768   // 8 * BSZ
#define NS    36864   // 9 * BSZ
#define VSIZE 50000
#define VPAD  50048   // 391 * 128

typedef unsigned long long ull;

// ---------------- scratch (device globals: allocation-free) ----------------
__device__ float d_hq[BSZ * HDIM];                       // [4096, 32]
__device__ float d_hqp[(size_t)BSZ * GDIM];              // [4096, 256] hq @ g1W[:,32:64]^T
__device__ float d_X0[(size_t)NSF * 32];                 // [32768, 32] sf hidden states
__device__ float d_X1[(size_t)NSF * GDIM];               // [32768, 256]
__device__ float d_X2[(size_t)NSF * GDIM];               // [32768, 256]
__device__ float d_gsum[(size_t)BSZ * GDIM];             // [4096, 256]
__device__ float d_Y1[(size_t)BSZ * GDIM];               // [4096, 256]
__device__ float d_Y2[(size_t)BSZ * F2DIM];              // [4096, 512]
__device__ float d_brel[8 * GDIM];                       // per-relation g1 bias
__device__ float d_g1w[GDIM * 32];                       // g1W cols 0..31 (hs part), dense
__device__ float d_zeros[GDIM];                          // stays zero (never written)

// Pre-split Whh for tensor-core LSTM: [n=g*32+j][k], padded to 36, (hi,lo) tf32
__device__ uint2 d_whhpkq[128 * 36];
__device__ uint2 d_whhpks[128 * 36];

// Precomputed input projections: xproj[v][n = g*32+j] = Wih·emb[v] + b  (native layout)
__device__ float d_xpq[(size_t)VPAD * 128];
__device__ float d_xps[(size_t)VPAD * 128];

struct SfPtrs { const int* p[8]; };

__device__ __forceinline__ float ftanh_(float x) {
    float r;
    asm("tanh.approx.f32 %0, %1;" : "=f"(r) : "f"(x));
    return r;
}
__device__ __forceinline__ float fsig(float x) {
    return fmaf(ftanh_(0.5f * x), 0.5f, 0.5f);
}
__device__ __forceinline__ uint32_t f2tf32(float x) {
    uint32_t r; asm("cvt.rna.tf32.f32 %0, %1;" : "=r"(r) : "f"(x)); return r;
}
__device__ __forceinline__ void tf32_split(float x, uint32_t& hi, uint32_t& lo) {
    hi = f2tf32(x);
    lo = f2tf32(x - __uint_as_float(hi));
}
__device__ __forceinline__ void mma_tf32(float* d, const uint32_t* a, const uint32_t* b) {
    asm volatile(
        "mma.sync.aligned.m16n8k8.row.col.f32.tf32.tf32.f32 "
        "{%0,%1,%2,%3}, {%4,%5,%6,%7}, {%8,%9}, {%0,%1,%2,%3};"
        : "+f"(d[0]), "+f"(d[1]), "+f"(d[2]), "+f"(d[3])
        : "r"(a[0]), "r"(a[1]), "r"(a[2]), "r"(a[3]), "r"(b[0]), "r"(b[1]));
}

// ---------------------------------------------------------------------------
// Pack Whh into pre-split tf32 (hi,lo) with row pad 36.
// ---------------------------------------------------------------------------
__global__ void pack_kernel(const float* __restrict__ qWhh, const float* __restrict__ sWhh)
{
    int idx = blockIdx.x * blockDim.x + threadIdx.x;   // 0 .. 128*36-1
    if (idx < 128 * 36) {
        int n = idx / 36, k = idx % 36;
        float vq = (k < 32) ? qWhh[n * 32 + k] : 0.f;
        float vs = (k < 32) ? sWhh[n * 32 + k] : 0.f;
        uint32_t hi, lo;
        tf32_split(vq, hi, lo);
        d_whhpkq[idx] = make_uint2(hi, lo);
        tf32_split(vs, hi, lo);
        d_whhpks[idx] = make_uint2(hi, lo);
    }
}

// Per-relation g1 bias + dense g1W (hs columns 0..31).
__global__ void bias_rel_kernel(const float* __restrict__ g1W, const float* __restrict__ g1b)
{
    int idx = blockIdx.x * blockDim.x + threadIdx.x;
    if (idx < 8 * GDIM) {
        int r = idx >> 8, n = idx & 255;
        d_brel[idx] = g1b[n] + (float)r * g1W[n * 65 + 64];
    }
    if (idx < GDIM * 32) {
        int n = idx >> 5, k = idx & 31;
        d_g1w[idx] = g1W[n * 65 + k];
    }
}

// ---------------------------------------------------------------------------
// Tensor-core LSTM recurrence (R12 exact, X0 row stride 32).
// ---------------------------------------------------------------------------
#define LSTM_SMEM_BYTES ((128 * 36 + 64 * 36) * 8)   // 55296 B

__global__ void __launch_bounds__(128, 3) lstm_tc_kernel(const int* __restrict__ q, SfPtrs sf)
{
    extern __shared__ uint2 sm2[];
    uint2* sWhh = sm2;              // [128][36]
    uint2* sH   = sm2 + 128 * 36;   // [64][36]

    const int tid  = threadIdx.x;
    const int lane = tid & 31;
    const int wm   = (tid >> 5) * 16;
    const int lr   = lane >> 2;
    const int lc   = lane & 3;

    const bool isQ = (blockIdx.x < (BSZ / 64));
    const uint2* wsrc = isQ ? d_whhpkq : d_whhpks;
    const float* xp   = isQ ? d_xpq    : d_xps;

    for (int i = tid; i < 128 * 36; i += 128) sWhh[i] = wsrc[i];
    for (int i = tid; i < 64 * 36; i += 128) sH[i] = make_uint2(0u, 0u);
    __syncthreads();

    const int s0 = blockIdx.x * 64 + wm + lr;
    const int s1 = s0 + 8;
    const int *pt0, *pt1;
    if (isQ) {
        pt0 = q + (size_t)s0 * LSEQ;
        pt1 = q + (size_t)s1 * LSEQ;
    } else {
        int ss0 = s0 - BSZ;
        int r = ss0 >> 12;
        pt0 = sf.p[r] + (size_t)(ss0 & (BSZ - 1)) * LSEQ;
        pt1 = sf.p[r] + (size_t)((s1 - BSZ) & (BSZ - 1)) * LSEQ;
    }

    float c[16];
#pragma unroll
    for (int i = 0; i < 16; i++) c[i] = 0.f;

    for (int t = 0; t < LSEQ; t++) {
        const int tok0 = __ldg(&pt0[t]);
        const int tok1 = __ldg(&pt1[t]);
        const float2* xr0 = reinterpret_cast<const float2*>(xp + (size_t)tok0 * 128);
        const float2* xr1 = reinterpret_cast<const float2*>(xp + (size_t)tok1 * 128);

        float acc[16][4];
#pragma unroll
        for (int nt = 0; nt < 16; nt++) {
            float2 g0 = __ldg(&xr0[nt * 4 + lc]);
            float2 g1 = __ldg(&xr1[nt * 4 + lc]);
            acc[nt][0] = g0.x; acc[nt][1] = g0.y;
            acc[nt][2] = g1.x; acc[nt][3] = g1.y;
        }

#pragma unroll
        for (int kc = 0; kc < 4; kc++) {
            const int kb = kc * 8;
            const uint2 a0 = sH[(wm + lr) * 36 + kb + lc];
            const uint2 a1 = sH[(wm + lr + 8) * 36 + kb + lc];
            const uint2 a2 = sH[(wm + lr) * 36 + kb + lc + 4];
            const uint2 a3 = sH[(wm + lr + 8) * 36 + kb + lc + 4];
            const uint32_t ah[4] = { a0.x, a1.x, a2.x, a3.x };
            const uint32_t al[4] = { a0.y, a1.y, a2.y, a3.y };
#pragma unroll
            for (int nt = 0; nt < 16; nt++) {
                const uint2 b0 = sWhh[(nt * 8 + lr) * 36 + kb + lc];
                const uint2 b1 = sWhh[(nt * 8 + lr) * 36 + kb + lc + 4];
                const uint32_t bh[2] = { b0.x, b1.x };
                const uint32_t bl[2] = { b0.y, b1.y };
                mma_tf32(acc[nt], ah, bh);
                mma_tf32(acc[nt], ah, bl);
                mma_tf32(acc[nt], al, bh);
            }
        }

#pragma unroll
        for (int qx = 0; qx < 4; qx++) {
#pragma unroll
            for (int cix = 0; cix < 4; cix++) {
                const float gi = acc[0 * 4 + qx][cix];
                const float gf = acc[1 * 4 + qx][cix];
                const float gg = acc[2 * 4 + qx][cix];
                const float go = acc[3 * 4 + qx][cix];
                const int idx = qx * 4 + cix;
                float cc = c[idx];
                cc = fsig(gf) * cc + fsig(gi) * ftanh_(gg);
                c[idx] = cc;
                const float hv = fsig(go) * ftanh_(cc);
                uint32_t hi, lo;
                tf32_split(hv, hi, lo);
                const int row = wm + lr + (cix >> 1) * 8;
                const int k   = qx * 8 + 2 * lc + (cix & 1);
                sH[row * 36 + k] = make_uint2(hi, lo);
            }
        }
        __syncwarp();
    }

    {
        const int rl = wm + (lane >> 1);
        const int kb = (lane & 1) * 16;
        float hv[16];
#pragma unroll
        for (int i = 0; i < 16; i++) {
            uint2 v = sH[rl * 36 + kb + i];
            hv[i] = __uint_as_float(v.x) + __uint_as_float(v.y);
        }
        const int sg = blockIdx.x * 64 + rl;
        float* dst = isQ ? (d_hq + (size_t)sg * HDIM + kb)
                         : (d_X0 + (size_t)(sg - BSZ) * 32 + kb);
        float4* d4 = reinterpret_cast<float4*>(dst);
#pragma unroll
        for (int i = 0; i < 4; i++)
            d4[i] = make_float4(hv[4 * i], hv[4 * i + 1], hv[4 * i + 2], hv[4 * i + 3]);
    }
}

// ---------------------------------------------------------------------------
// fp32 GEMM (double-buffered) — xproj precompute and hqp precompute (K=32).
// ---------------------------------------------------------------------------
__global__ __launch_bounds__(256, 2) void gemm_kernel(
    const float* __restrict__ A, const float* __restrict__ W,
    const float* __restrict__ bias, float* __restrict__ C,
    int Mr, int N, int K, int lda, int ldw, int doRelu, int biasPerRel)
{
    __shared__ __align__(16) float sA[2][16][132];
    __shared__ __align__(16) float sW[2][16][68];

    const int bm = blockIdx.y * 128;
    const int bn = blockIdx.x * 64;
    const int tid = threadIdx.x;
    const int tx = tid & 15;
    const int ty = tid >> 4;

    float acc[8][4];
#pragma unroll
    for (int i = 0; i < 8; i++)
#pragma unroll
        for (int j = 0; j < 4; j++) acc[i][j] = 0.f;

    const int nk = (K + 15) >> 4;

#pragma unroll
    for (int i = 0; i < 8; i++) {
        int e = tid + i * 256; int m = e >> 4; int kk = e & 15;
        sA[0][kk][m] = (kk < K && (bm + m) < Mr) ? A[(size_t)(bm + m) * lda + kk] : 0.f;
    }
#pragma unroll
    for (int i = 0; i < 4; i++) {
        int e = tid + i * 256; int n = e >> 4; int kk = e & 15;
        sW[0][kk][n] = (kk < K && (bn + n) < N) ? W[(size_t)(bn + n) * ldw + kk] : 0.f;
    }
    __syncthreads();

    for (int kt = 0; kt < nk; kt++) {
        const int cur = kt & 1;
        float pa[8], pw[4];
        const bool has = (kt + 1 < nk);
        if (has) {
            int k0 = (kt + 1) << 4;
#pragma unroll
            for (int i = 0; i < 8; i++) {
                int e = tid + i * 256; int m = e >> 4; int kk = e & 15; int gk = k0 + kk;
                pa[i] = (gk < K && (bm + m) < Mr) ? A[(size_t)(bm + m) * lda + gk] : 0.f;
            }
#pragma unroll
            for (int i = 0; i < 4; i++) {
                int e = tid + i * 256; int n = e >> 4; int kk = e & 15; int gk = k0 + kk;
                pw[i] = (gk < K && (bn + n) < N) ? W[(size_t)(bn + n) * ldw + gk] : 0.f;
            }
        }
#pragma unroll
        for (int kk = 0; kk < 16; kk++) {
            float a[8], w[4];
            float4 a0 = *reinterpret_cast<const float4*>(&sA[cur][kk][ty * 8]);
            float4 a1 = *reinterpret_cast<const float4*>(&sA[cur][kk][ty * 8 + 4]);
            float4 w0 = *reinterpret_cast<const float4*>(&sW[cur][kk][tx * 4]);
            a[0]=a0.x; a[1]=a0.y; a[2]=a0.z; a[3]=a0.w;
            a[4]=a1.x; a[5]=a1.y; a[6]=a1.z; a[7]=a1.w;
            w[0]=w0.x; w[1]=w0.y; w[2]=w0.z; w[3]=w0.w;
#pragma unroll
            for (int i = 0; i < 8; i++)
#pragma unroll
                for (int j = 0; j < 4; j++) acc[i][j] += a[i] * w[j];
        }
        if (has) {
            const int nxt = cur ^ 1;
#pragma unroll
            for (int i = 0; i < 8; i++) {
                int e = tid + i * 256; int m = e >> 4; int kk = e & 15;
                sA[nxt][kk][m] = pa[i];
            }
#pragma unroll
            for (int i = 0; i < 4; i++) {
                int e = tid + i * 256; int n = e >> 4; int kk = e & 15;
                sW[nxt][kk][n] = pw[i];
            }
            __syncthreads();
        }
    }

    const float* brow = biasPerRel ? (bias + (size_t)(bm >> 12) * N) : bias;
#pragma unroll
    for (int i = 0; i < 8; i++) {
        int m = bm + ty * 8 + i;
#pragma unroll
        for (int j = 0; j < 4; j++) {
            int n = bn + tx * 4 + j;
            if (n < N) {
                float v = acc[i][j] + brow[n];
                if (doRelu) v = fmaxf(v, 0.f);
                C[(size_t)m * N + n] = v;
            }
        }
    }
}

// ---------------------------------------------------------------------------
// 3xTF32 tensor-core GEMM (R12-exact core, 128x64, static smem) with an
// optional per-sample bias2 (row index = global_row & (BSZ-1)).
// C[M,N] = act(A[M,K(lda)] @ W[N,K(ldw)]^T + bias [+ bias2[row&4095]]).
// M%128==0, K%32==0, lda%4==0, ldw%4==0.
// ---------------------------------------------------------------------------
__global__ __launch_bounds__(256) void gemm_tc_kernel(
    const float* __restrict__ A, const float* __restrict__ W,
    const float* __restrict__ bias, const float* __restrict__ bias2,
    float* __restrict__ C,
    int N, int K, int lda, int ldw, int doRelu, int biasPerRel)
{
    __shared__ __align__(16) float sA[128][36];
    __shared__ __align__(16) float sW[64][36];

    const int bm = blockIdx.y * 128;
    const int bn = blockIdx.x * 64;
    const int tid  = threadIdx.x;
    const int lane = tid & 31;
    const int wid  = tid >> 5;
    const int warpM = wid & 3;
    const int warpN = wid >> 2;
    const int wm = warpM * 32;
    const int wn = warpN * 32;
    const int lr = lane >> 2;
    const int lc = lane & 3;

    float acc[2][4][4];
#pragma unroll
    for (int mt = 0; mt < 2; mt++)
#pragma unroll
        for (int nt = 0; nt < 4; nt++)
#pragma unroll
            for (int r = 0; r < 4; r++) acc[mt][nt][r] = 0.f;

    for (int k0 = 0; k0 < K; k0 += 32) {
#pragma unroll
        for (int i = 0; i < 4; i++) {
            int e = tid + i * 256;
            int m = e >> 3;
            int kq = e & 7;
            float4 v = *reinterpret_cast<const float4*>(&A[(size_t)(bm + m) * lda + k0 + kq * 4]);
            *reinterpret_cast<float4*>(&sA[m][kq * 4]) = v;
        }
#pragma unroll
        for (int i = 0; i < 2; i++) {
            int e = tid + i * 256;
            int n = e >> 3;
            int kq = e & 7;
            float4 v = make_float4(0.f, 0.f, 0.f, 0.f);
            if ((bn + n) < N)
                v = *reinterpret_cast<const float4*>(&W[(size_t)(bn + n) * ldw + k0 + kq * 4]);
            *reinterpret_cast<float4*>(&sW[n][kq * 4]) = v;
        }
        __syncthreads();

#pragma unroll
        for (int kc = 0; kc < 4; kc++) {
            const int kb = kc * 8;
            uint32_t ahi[2][4], alo[2][4];
#pragma unroll
            for (int mt = 0; mt < 2; mt++) {
                int r0 = wm + mt * 16 + lr;
                float a0 = sA[r0][kb + lc];
                float a1 = sA[r0 + 8][kb + lc];
                float a2 = sA[r0][kb + lc + 4];
                float a3 = sA[r0 + 8][kb + lc + 4];
                tf32_split(a0, ahi[mt][0], alo[mt][0]);
                tf32_split(a1, ahi[mt][1], alo[mt][1]);
                tf32_split(a2, ahi[mt][2], alo[mt][2]);
                tf32_split(a3, ahi[mt][3], alo[mt][3]);
            }
            uint32_t bhi[4][2], blo[4][2];
#pragma unroll
            for (int nt = 0; nt < 4; nt++) {
                int n0 = wn + nt * 8 + lr;
                float b0 = sW[n0][kb + lc];
                float b1 = sW[n0][kb + lc + 4];
                tf32_split(b0, bhi[nt][0], blo[nt][0]);
                tf32_split(b1, bhi[nt][1], blo[nt][1]);
            }
#pragma unroll
            for (int mt = 0; mt < 2; mt++)
#pragma unroll
                for (int nt = 0; nt < 4; nt++) {
                    mma_tf32(acc[mt][nt], ahi[mt], bhi[nt]);
                    mma_tf32(acc[mt][nt], ahi[mt], blo[nt]);
                    mma_tf32(acc[mt][nt], alo[mt], bhi[nt]);
                }
        }
        __syncthreads();
    }

    const float* brow = biasPerRel ? (bias + (size_t)(bm >> 12) * N) : bias;
#pragma unroll
    for (int mt = 0; mt < 2; mt++) {
#pragma unroll
        for (int nt = 0; nt < 4; nt++) {
            int r = bm + wm + mt * 16 + lr;
            int n = bn + wn + nt * 8 + 2 * lc;
            if (n < N) {
                float bsx = brow[n], bsy = brow[n + 1];
                float2 v0 = make_float2(acc[mt][nt][0] + bsx, acc[mt][nt][1] + bsy);
                float2 v1 = make_float2(acc[mt][nt][2] + bsx, acc[mt][nt][3] + bsy);
                if (bias2) {
                    float2 e0 = *reinterpret_cast<const float2*>(&bias2[(size_t)(r & (BSZ - 1)) * N + n]);
                    float2 e1 = *reinterpret_cast<const float2*>(&bias2[(size_t)((r + 8) & (BSZ - 1)) * N + n]);
                    v0.x += e0.x; v0.y += e0.y;
                    v1.x += e1.x; v1.y += e1.y;
                }
                if (doRelu) {
                    v0.x = fmaxf(v0.x, 0.f); v0.y = fmaxf(v0.y, 0.f);
                    v1.x = fmaxf(v1.x, 0.f); v1.y = fmaxf(v1.y, 0.f);
                }
                *reinterpret_cast<float2*>(&C[(size_t)r * N + n]) = v0;
                *reinterpret_cast<float2*>(&C[(size_t)(r + 8) * N + n]) = v1;
            }
        }
    }
}

// gsum[b,n] = sum_{r=0..7} X2[r*BSZ + b, n]
__global__ void reduce8_kernel()
{
    int idx = blockIdx.x * 256 + threadIdx.x;
    int b = idx >> 8;
    int n = idx & 255;
    float sum = 0.f;
#pragma unroll
    for (int r = 0; r < 8; r++)
        sum += d_X2[((size_t)(r * BSZ + b)) * GDIM + n];
    d_gsum[idx] = sum;
}

// ---------------------------------------------------------------------------
extern "C" void kernel_launch(void* const* d_in, const int* in_sizes, int n_in,
                              void* d_out, int out_size)
{
    const int*   q    = (const int*)d_in[0];
    SfPtrs sf;
    for (int i = 0; i < 8; i++) sf.p[i] = (const int*)d_in[1 + i];
    const float* emb  = (const float*)d_in[9];
    const float* qWih = (const float*)d_in[10];
    const float* qWhh = (const float*)d_in[11];
    const float* qb   = (const float*)d_in[12];
    const float* sWih = (const float*)d_in[13];
    const float* sWhh = (const float*)d_in[14];
    const float* sb   = (const float*)d_in[15];
    const float* g1W  = (const float*)d_in[16];
    const float* g1b  = (const float*)d_in[17];
    const float* g2W  = (const float*)d_in[18];
    const float* g2b  = (const float*)d_in[19];
    const float* g3W  = (const float*)d_in[20];
    const float* g3b  = (const float*)d_in[21];
    const float* g4W  = (const float*)d_in[22];
    const float* g4b  = (const float*)d_in[23];
    const float* f1W  = (const float*)d_in[24];
    const float* f1b  = (const float*)d_in[25];
    const float* f2W  = (const float*)d_in[26];
    const float* f2b  = (const float*)d_in[27];
    const float* f3W  = (const float*)d_in[28];
    const float* f3b  = (const float*)d_in[29];
    float* out = (float*)d_out;

    void *pX0, *pX1, *pX2, *pGsum, *pY1, *pY2, *pBrel, *pG1w, *pXpq, *pXps;
    void *pHq, *pHqp, *pZeros;
    cudaGetSymbolAddress(&pX0,   d_X0);
    cudaGetSymbolAddress(&pX1,   d_X1);
    cudaGetSymbolAddress(&pX2,   d_X2);
    cudaGetSymbolAddress(&pGsum, d_gsum);
    cudaGetSymbolAddress(&pY1,   d_Y1);
    cudaGetSymbolAddress(&pY2,   d_Y2);
    cudaGetSymbolAddress(&pBrel, d_brel);
    cudaGetSymbolAddress(&pG1w,  d_g1w);
    cudaGetSymbolAddress(&pXpq,  d_xpq);
    cudaGetSymbolAddress(&pXps,  d_xps);
    cudaGetSymbolAddress(&pHq,   d_hq);
    cudaGetSymbolAddress(&pHqp,  d_hqp);
    cudaGetSymbolAddress(&pZeros, d_zeros);
    const float* X0 = (const float*)pX0;
    float* X1 = (float*)pX1;
    float* X2 = (float*)pX2;
    float* Gs = (float*)pGsum;
    float* Y1 = (float*)pY1;
    float* Y2 = (float*)pY2;
    const float* Brel = (const float*)pBrel;
    const float* G1w  = (const float*)pG1w;
    const float* Hqp  = (const float*)pHqp;

    static bool attr_set = false;
    if (!attr_set) {
        cudaFuncSetAttribute(lstm_tc_kernel, cudaFuncAttributeMaxDynamicSharedMemorySize,
                             LSTM_SMEM_BYTES);
        attr_set = true;
    }

    // 0) pack Whh + per-relation g1 bias + dense g1W (hs cols)
    pack_kernel<<<18, 256>>>(qWhh, sWhh);
    bias_rel_kernel<<<32, 256>>>(g1W, g1b);

    // 0b) precompute input projections: xproj = emb @ Wih^T + b (native layout)
    gemm_kernel<<<dim3(2, VPAD / 128), 256>>>(emb, qWih, qb, (float*)pXpq,
                                              VSIZE, 128, 32, 32, 32, 0, 0);
    gemm_kernel<<<dim3(2, VPAD / 128), 256>>>(emb, sWih, sb, (float*)pXps,
                                              VSIZE, 128, 32, 32, 32, 0, 0);

    // 1) tensor-core LSTM recurrence (q + 8 sf streams)
    lstm_tc_kernel<<<NS / 64, 128, LSTM_SMEM_BYTES>>>(q, sf);

    // 2) hq projection: hqp[b] = hq[b] @ g1W[:,32:64]^T  (fp32, K=32)
    gemm_kernel<<<dim3(GDIM / 64, BSZ / 128), 256>>>(
        (const float*)pHq, g1W + 32, (const float*)pZeros, (float*)pHqp,
        BSZ, GDIM, 32, 32, 65, 0, 0);

    // 3) g-MLP on tensor cores (3xTF32). g1: K=32 over sf states + hqp bias2.
    gemm_tc_kernel<<<dim3(GDIM / 64, NSF / 128), 256>>>(X0, G1w, Brel, Hqp, X1, GDIM, 32, 32, 32, 1, 1);
    gemm_tc_kernel<<<dim3(GDIM / 64, NSF / 128), 256>>>(X1, g2W, g2b, nullptr, X2, GDIM, GDIM, GDIM, GDIM, 1, 0);
    gemm_tc_kernel<<<dim3(GDIM / 64, NSF / 128), 256>>>(X2, g3W, g3b, nullptr, X1, GDIM, GDIM, GDIM, GDIM, 1, 0);
    gemm_tc_kernel<<<dim3(GDIM / 64, NSF / 128), 256>>>(X1, g4W, g4b, nullptr, X2, GDIM, GDIM, GDIM, GDIM, 1, 0);

    // 4) segment-sum over 8 relations
    reduce8_kernel<<<(BSZ * GDIM) / 256, 256>>>();

    // 5) f-head on tensor cores
    gemm_tc_kernel<<<dim3(GDIM / 64,  BSZ / 128), 256>>>(Gs, f1W, f1b, nullptr, Y1, GDIM,  GDIM,  GDIM,  GDIM,  1, 0);
    gemm_tc_kernel<<<dim3(F2DIM / 64, BSZ / 128), 256>>>(Y1, f2W, f2b, nullptr, Y2, F2DIM, GDIM,  GDIM,  GDIM,  1, 0);
    gemm_tc_kernel<<<dim3((ADIM + 63) / 64, BSZ / 128), 256>>>(Y2, f3W, f3b, nullptr, out, ADIM, F2DIM, F2DIM, F2DIM, 0, 0);
}